// round 1
// baseline (speedup 1.0000x reference)
#include <cuda_runtime.h>
#include <stdint.h>

// Problem constants (B=8, H=W=512)
#define NB 8
#define NPIX 262144              // 512*512
#define NF4 (NPIX/4)             // 65536 float4 per sample per channel
#define NBINS 2048

// Scratch (static __device__ — no allocations allowed)
__device__ float    g_d [NB*NPIX];
__device__ float    g_dc[NB*NPIX];
__device__ unsigned g_hist1[2][NB][NBINS];
__device__ unsigned g_cnt2 [2][NB][NBINS];
__device__ float    g_sum2 [2][NB][NBINS];
__device__ float    g_Sab  [2][NB];      // sum of values strictly above level-1 bin
__device__ unsigned g_count[NB];         // unknown pixel count per sample
__device__ int      g_bin1 [2][NB];      // selected level-1 bin
__device__ unsigned g_cab  [2][NB];      // count strictly above level-1 bin

// ---------------------------------------------------------------------------
// Z: zero all accumulators + output (out is poisoned to 0xAA by harness)
// ---------------------------------------------------------------------------
__global__ void kZ(float* out) {
    int i = blockIdx.x * 256 + threadIdx.x;
    const int tot = 2 * NB * NBINS;                 // 32768
    if (i < tot) {
        ((unsigned*)g_hist1)[i] = 0u;
        ((unsigned*)g_cnt2)[i]  = 0u;
        ((float*)g_sum2)[i]     = 0.f;
    }
    if (i < 16) { ((float*)g_Sab)[i] = 0.f; ((int*)g_bin1)[i] = -1; ((unsigned*)g_cab)[i] = 0u; }
    if (i < NB) g_count[i] = 0u;
    if (i == 0) out[0] = 0.f;
}

// ---------------------------------------------------------------------------
// A: compute d, dc per pixel (|x| instead of sqrt(x^2+eps^2): monotone, error
//    ~1e-10 rel), store to scratch (masked pixels -> 0.0), count unknown,
//    level-1 histogram (bits[31:21]) of unknown values only.
// 2048 blocks x 256 threads, 4 px per thread (float4). 256 blocks per sample.
// ---------------------------------------------------------------------------
__global__ void __launch_bounds__(256) kA(const float4* __restrict__ img,
                                          const float4* __restrict__ alp,
                                          const float4* __restrict__ prd,
                                          const int4*   __restrict__ tri,
                                          const float4* __restrict__ fg,
                                          const float4* __restrict__ bg) {
    __shared__ unsigned sh[2][NBINS];
    int t = threadIdx.x;
    for (int i = t; i < 2 * NBINS; i += 256) ((unsigned*)sh)[i] = 0u;
    __syncthreads();

    int blk = blockIdx.x;
    int b   = blk >> 8;                      // sample id (256 blocks / sample)
    int g   = blk * 256 + t;                 // global float4 index in [0, NB*NF4)
    int p4  = g & (NF4 - 1);                 // float4 index within sample
    int cb  = (b * 3) * NF4;                 // channel base for 3-ch tensors

    int4   tv = tri[g];
    float4 av = alp[g];
    float4 pv = prd[g];
    float4 i0 = img[cb + p4], i1 = img[cb + NF4 + p4], i2 = img[cb + 2 * NF4 + p4];
    float4 f0 = fg [cb + p4], f1 = fg [cb + NF4 + p4], f2 = fg [cb + 2 * NF4 + p4];
    float4 g0 = bg [cb + p4], g1 = bg [cb + NF4 + p4], g2 = bg [cb + 2 * NF4 + p4];

    const float inv255 = 1.0f / 255.0f;
    int   tvi[4] = { tv.x, tv.y, tv.z, tv.w };
    float aa[4]  = { av.x, av.y, av.z, av.w };
    float pp[4]  = { pv.x, pv.y, pv.z, pv.w };
    float I0[4]  = { i0.x, i0.y, i0.z, i0.w };
    float I1[4]  = { i1.x, i1.y, i1.z, i1.w };
    float I2[4]  = { i2.x, i2.y, i2.z, i2.w };
    float F0[4]  = { f0.x, f0.y, f0.z, f0.w };
    float F1[4]  = { f1.x, f1.y, f1.z, f1.w };
    float F2[4]  = { f2.x, f2.y, f2.z, f2.w };
    float G0[4]  = { g0.x, g0.y, g0.z, g0.w };
    float G1[4]  = { g1.x, g1.y, g1.z, g1.w };
    float G2[4]  = { g2.x, g2.y, g2.z, g2.w };

    float dv[4], dcv[4];
    unsigned cnt = 0;
#pragma unroll
    for (int j = 0; j < 4; j++) {
        bool u = (tvi[j] == 128);
        float p = pp[j], q = 1.0f - p;
        float d = 0.f, dc = 0.f;
        if (u) {
            d  = fabsf(aa[j] * inv255 - p);
            dc = fabsf(I0[j] - (F0[j] * p + q * G0[j]))
               + fabsf(I1[j] - (F1[j] * p + q * G1[j]))
               + fabsf(I2[j] - (F2[j] * p + q * G2[j]));
            cnt++;
            atomicAdd(&sh[0][__float_as_uint(d)  >> 21], 1u);
            atomicAdd(&sh[1][__float_as_uint(dc) >> 21], 1u);
        }
        dv[j] = d; dcv[j] = dc;
    }
    ((float4*)g_d )[g] = make_float4(dv[0],  dv[1],  dv[2],  dv[3]);
    ((float4*)g_dc)[g] = make_float4(dcv[0], dcv[1], dcv[2], dcv[3]);

    // block reduce unknown count
    for (int o = 16; o; o >>= 1) cnt += __shfl_down_sync(0xffffffffu, cnt, o);
    __shared__ unsigned swc[8];
    if ((t & 31) == 0) swc[t >> 5] = cnt;
    __syncthreads();
    if (t == 0) {
        unsigned tot = 0;
#pragma unroll
        for (int w = 0; w < 8; w++) tot += swc[w];
        atomicAdd(&g_count[b], tot);
    }
    // merge per-block histogram into global (sparse: skip zero bins)
    for (int i = t; i < NBINS; i += 256) {
        unsigned c0 = sh[0][i]; if (c0) atomicAdd(&g_hist1[0][b][i], c0);
        unsigned c1 = sh[1][i]; if (c1) atomicAdd(&g_hist1[1][b][i], c1);
    }
}

// ---------------------------------------------------------------------------
// P1: per (array, sample) unit find level-1 bin where descending cumulative
//     count crosses k. 16 blocks x 256 threads (8 bins/thread).
// ---------------------------------------------------------------------------
__global__ void __launch_bounds__(256) kP1() {
    int unit = blockIdx.x;
    int a = unit >> 3, b = unit & 7;
    unsigned count = g_count[b];
    int k = (int)floorf((float)count * 0.7f);
    if (k <= 0) return;                               // g_bin1 stays -1

    __shared__ unsigned s_cnt[NBINS];
    __shared__ unsigned s_part[256];
    __shared__ unsigned s_suf[257];
    int t = threadIdx.x;
    for (int i = t; i < NBINS; i += 256) s_cnt[i] = g_hist1[a][b][i];
    __syncthreads();
    unsigned loc = 0;
#pragma unroll
    for (int j = 0; j < 8; j++) loc += s_cnt[t * 8 + j];
    s_part[t] = loc;
    __syncthreads();
    if (t == 0) {
        unsigned acc = 0;
        s_suf[256] = 0;
        for (int i = 255; i >= 0; i--) { acc += s_part[i]; s_suf[i] = acc; }
    }
    __syncthreads();
    unsigned accC = s_suf[t + 1];                     // count strictly above my bins
#pragma unroll
    for (int j = 7; j >= 0; j--) {
        int i = t * 8 + j;
        unsigned c = s_cnt[i];
        if (c > 0 && accC < (unsigned)k && accC + c >= (unsigned)k) {
            g_bin1[a][b] = i;
            g_cab[a][b]  = accC;
        }
        accC += c;
    }
}

// ---------------------------------------------------------------------------
// L2: one pass over scratch. Values above bin1 -> running sum; values inside
//     bin1 -> level-2 histogram bits[20:10] (global atomics: sparse, low
//     contention since only the tie bin's ~5-15% of values hit this path).
// ---------------------------------------------------------------------------
__global__ void __launch_bounds__(256) kL2() {
    int t   = threadIdx.x;
    int blk = blockIdx.x;
    int b   = blk >> 8;
    int g   = blk * 256 + t;
    float4 dv = ((const float4*)g_d )[g];
    float4 cv = ((const float4*)g_dc)[g];
    int b1d = g_bin1[0][b];
    int b1c = g_bin1[1][b];
    float dd[4] = { dv.x, dv.y, dv.z, dv.w };
    float cc[4] = { cv.x, cv.y, cv.z, cv.w };
    float sd = 0.f, sc = 0.f;
#pragma unroll
    for (int j = 0; j < 4; j++) {
        unsigned bd = __float_as_uint(dd[j]); int td = (int)(bd >> 21);
        if (td > b1d) sd += dd[j];
        else if (td == b1d) {
            int b2 = (int)((bd >> 10) & 2047u);
            atomicAdd(&g_cnt2[0][b][b2], 1u);
            atomicAdd(&g_sum2[0][b][b2], dd[j]);
        }
        unsigned bc = __float_as_uint(cc[j]); int tc = (int)(bc >> 21);
        if (tc > b1c) sc += cc[j];
        else if (tc == b1c) {
            int b2 = (int)((bc >> 10) & 2047u);
            atomicAdd(&g_cnt2[1][b][b2], 1u);
            atomicAdd(&g_sum2[1][b][b2], cc[j]);
        }
    }
    for (int o = 16; o; o >>= 1) {
        sd += __shfl_down_sync(0xffffffffu, sd, o);
        sc += __shfl_down_sync(0xffffffffu, sc, o);
    }
    __shared__ float swd[8], sws[8];
    if ((t & 31) == 0) { swd[t >> 5] = sd; sws[t >> 5] = sc; }
    __syncthreads();
    if (t == 0) {
        float td = 0.f, tc2 = 0.f;
#pragma unroll
        for (int w = 0; w < 8; w++) { td += swd[w]; tc2 += sws[w]; }
        atomicAdd(&g_Sab[0][b], td);
        atomicAdd(&g_Sab[1][b], tc2);
    }
}

// ---------------------------------------------------------------------------
// F: per unit find level-2 crossing bin, top-k sum = S_above + full bins above
//    + remainder * (tie-bin mean); loss = S/(k+eps); out += 0.5*loss/8.
// ---------------------------------------------------------------------------
__global__ void __launch_bounds__(256) kF(float* out) {
    int unit = blockIdx.x;
    int a = unit >> 3, b = unit & 7;
    unsigned count = g_count[b];
    int k = (int)floorf((float)count * 0.7f);
    if (k <= 0) return;                               // contribution is 0
    unsigned cab = g_cab[a][b];
    float    Sab = g_Sab[a][b];

    __shared__ unsigned s_cnt[NBINS];
    __shared__ float    s_sum[NBINS];
    __shared__ unsigned s_pc[256];
    __shared__ float    s_ps[256];
    __shared__ unsigned s_sc[257];
    __shared__ float    s_ss[257];
    int t = threadIdx.x;
    for (int i = t; i < NBINS; i += 256) {
        s_cnt[i] = g_cnt2[a][b][i];
        s_sum[i] = g_sum2[a][b][i];
    }
    __syncthreads();
    unsigned lc = 0; float ls = 0.f;
#pragma unroll
    for (int j = 0; j < 8; j++) { lc += s_cnt[t * 8 + j]; ls += s_sum[t * 8 + j]; }
    s_pc[t] = lc; s_ps[t] = ls;
    __syncthreads();
    if (t == 0) {
        unsigned ac = 0; float as = 0.f;
        s_sc[256] = 0; s_ss[256] = 0.f;
        for (int i = 255; i >= 0; i--) { ac += s_pc[i]; as += s_ps[i]; s_sc[i] = ac; s_ss[i] = as; }
    }
    __syncthreads();
    unsigned accC = s_sc[t + 1];
    float    accS = s_ss[t + 1];
#pragma unroll
    for (int j = 7; j >= 0; j--) {
        int i = t * 8 + j;
        unsigned c = s_cnt[i];
        unsigned texcl = cab + accC;
        if (c > 0 && texcl < (unsigned)k && texcl + c >= (unsigned)k) {
            unsigned rem = (unsigned)k - texcl;
            float mean = s_sum[i] / (float)c;
            float S = Sab + accS + (float)rem * mean;
            float loss = S / ((float)k + 1e-6f);
            atomicAdd(out, 0.0625f * loss);           // 0.5 * loss / 8
        }
        accC += c;
        accS += s_sum[i];
    }
}

// ---------------------------------------------------------------------------
extern "C" void kernel_launch(void* const* d_in, const int* in_sizes, int n_in,
                              void* d_out, int out_size) {
    const float4* img = (const float4*)d_in[0];   // image  [8,3,512,512]
    const float4* alp = (const float4*)d_in[1];   // alpha  [8,1,512,512]
    const float4* prd = (const float4*)d_in[2];   // raw_alpha_pred
    const int4*   tri = (const int4*)  d_in[3];   // trimap (int32)
    const float4* fg  = (const float4*)d_in[4];   // fg
    const float4* bg  = (const float4*)d_in[5];   // bg
    float* out = (float*)d_out;

    kZ <<<128,  256>>>(out);
    kA <<<2048, 256>>>(img, alp, prd, tri, fg, bg);
    kP1<<<16,   256>>>();
    kL2<<<2048, 256>>>();
    kF <<<16,   256>>>(out);
}

// round 3
// speedup vs baseline: 1.8367x; 1.8367x over previous
#include <cuda_runtime.h>
#include <stdint.h>

#define NB    8
#define NF4   65536           // float4 groups per sample (512*512/4)
#define NBINS 2048
#define GRID  296             // 2 blocks/SM on 148 SMs (152 on GB300: still resident)
#define BPS   37              // blocks per sample (37*8 = 296)
#define GPB   1772            // groups per block (37*1772 >= 65536)
#define ITER  7               // ceil(1772/256)

__device__ unsigned g_hist1[2][NB][NBINS];
__device__ unsigned g_cnt2 [2][NB][32];
__device__ float    g_Sab  [2][NB];
__device__ unsigned g_count[NB];
__device__ int      g_bin1 [2][NB];
__device__ unsigned g_cab  [2][NB];
__device__ unsigned g_bar  [4];          // monotonic epoch counters (never reset)

// round-to-nearest-even f32 -> bf16 bits (nonneg finite only)
__device__ __forceinline__ unsigned f2bf(float f) {
    unsigned u = __float_as_uint(f);
    return (u + 0x7FFFu + ((u >> 16) & 1u)) >> 16;
}
__device__ __forceinline__ float bf2f(unsigned b) { return __uint_as_float(b << 16); }

__device__ __forceinline__ float  pget(const float4& v, int p) { return p == 0 ? v.x : p == 1 ? v.y : p == 2 ? v.z : v.w; }
__device__ __forceinline__ int    tget(const int4&   v, int p) { return p == 0 ? v.x : p == 1 ? v.y : p == 2 ? v.z : v.w; }

// grid barrier: monotonic counter, epoch-safe across graph replays (no reset)
__device__ __forceinline__ void grid_barrier(int id) {
    __syncthreads();
    if (threadIdx.x == 0) {
        __threadfence();                               // release
        unsigned old = atomicAdd(&g_bar[id], 1u);
        unsigned target = old - (old % GRID) + GRID;   // end of this epoch
        while (*((volatile unsigned*)&g_bar[id]) < target) __nanosleep(256);
        __threadfence();                               // acquire
    }
    __syncthreads();
}

__global__ void __launch_bounds__(256, 2)
kFused(const float4* __restrict__ img, const float4* __restrict__ alp,
       const float4* __restrict__ prd, const int4*   __restrict__ tri,
       const float4* __restrict__ fg,  const float4* __restrict__ bg,
       float* out)
{
    __shared__ unsigned sh[2][NBINS];          // 16KB: histograms, then reloaded global hist
    __shared__ unsigned wt[8];
    __shared__ int      s_bin1[2];
    __shared__ unsigned s_tie[2][32];
    __shared__ unsigned s_redu[8];
    __shared__ float    sr0[8], sr1[8];

    const int t   = threadIdx.x;
    const int l   = t & 31, w = t >> 5;
    const int blk = blockIdx.x;
    const int b   = blk / BPS;                 // sample id
    const int lb  = blk - b * BPS;
    const int base = lb * GPB;                 // group base within sample
    const int cb  = b * 3 * NF4;               // 3-channel tensor base

    for (int i = t; i < 2 * NBINS; i += 256) ((unsigned*)sh)[i] = 0u;
    if (blk == 0 && t == 0) out[0] = 0.0f;     // ordered before phase-3 adds via barrier fences
    __syncthreads();

    // ---------------- phase 1: compute values, register-store, histogram ----
    unsigned packed[ITER][4];
    unsigned cnt = 0;
    const float inv255 = 1.0f / 255.0f;
#pragma unroll
    for (int j = 0; j < ITER; j++) {
        int gl0 = base + j * 256 + t;
        bool inr = gl0 < NF4;
        int gl = inr ? gl0 : (NF4 - 1);        // clamp: keeps warp convergent
        int g  = b * NF4 + gl;
        int4   tv = tri[g];
        float4 av = alp[g], pv = prd[g];
        float4 i0 = img[cb + gl], i1 = img[cb + NF4 + gl], i2 = img[cb + 2 * NF4 + gl];
        float4 f0 = fg [cb + gl], f1 = fg [cb + NF4 + gl], f2 = fg [cb + 2 * NF4 + gl];
        float4 g0 = bg [cb + gl], g1 = bg [cb + NF4 + gl], g2 = bg [cb + 2 * NF4 + gl];
#pragma unroll
        for (int p = 0; p < 4; p++) {
            bool u = inr && (tget(tv, p) == 128);
            float pr = pget(pv, p), q = 1.0f - pr;
            float d = 0.0f, dc = 0.0f;
            if (u) {
                d  = fabsf(pget(av, p) * inv255 - pr);
                dc = fabsf(pget(i0, p) - (pget(f0, p) * pr + q * pget(g0, p)))
                   + fabsf(pget(i1, p) - (pget(f1, p) * pr + q * pget(g1, p)))
                   + fabsf(pget(i2, p) - (pget(f2, p) * pr + q * pget(g2, p)));
                cnt++;
            }
            unsigned kd = f2bf(d), kc = f2bf(dc);          // masked/padding -> key 0, value 0
            packed[j][p] = kd | (kc << 16);
            // full-warp match-aggregated shared atomics (sentinels for non-contributors)
            int bd = u ? (int)(kd >> 5) : -1;
            int bc = u ? (int)(kc >> 5) : -2;
            unsigned m1 = __match_any_sync(0xffffffffu, bd);
            if (u && (int)(__ffs(m1) - 1) == l) atomicAdd(&sh[0][bd], (unsigned)__popc(m1));
            unsigned m2 = __match_any_sync(0xffffffffu, bc);
            if (u && (int)(__ffs(m2) - 1) == l) atomicAdd(&sh[1][bc], (unsigned)__popc(m2));
        }
    }
    // unknown-count reduce -> global
    for (int o = 16; o; o >>= 1) cnt += __shfl_down_sync(0xffffffffu, cnt, o);
    if (l == 0) s_redu[w] = cnt;
    __syncthreads();
    if (t == 0) {
        unsigned tot = 0;
#pragma unroll
        for (int i = 0; i < 8; i++) tot += s_redu[i];
        atomicAdd(&g_count[b], tot);
    }
    // merge block histogram into global (sparse)
    for (int i = t; i < NBINS; i += 256) {
        unsigned c0 = sh[0][i]; if (c0) atomicAdd(&g_hist1[0][b][i], c0);
        unsigned c1 = sh[1][i]; if (c1) atomicAdd(&g_hist1[1][b][i], c1);
    }

    grid_barrier(0);

    // ---------------- phase 1.5: every block selects level-1 bin for its sample
    unsigned count = g_count[b];
    int k = (int)floorf((float)count * 0.7f);

    for (int i = t; i < NBINS; i += 256) { sh[0][i] = g_hist1[0][b][i]; sh[1][i] = g_hist1[1][b][i]; }
    if (t < 2) s_bin1[t] = 1 << 29;            // sentinel: nothing matches when k<=0
    __syncthreads();

#pragma unroll
    for (int a = 0; a < 2; a++) {
        unsigned loc = 0;
#pragma unroll
        for (int jj = 0; jj < 8; jj++) loc += sh[a][t * 8 + jj];
        unsigned s = loc;
#pragma unroll
        for (int o = 1; o < 32; o <<= 1) {     // inclusive suffix within warp
            unsigned v = __shfl_down_sync(0xffffffffu, s, o);
            if (l + o < 32) s += v;
        }
        if (l == 0) wt[w] = s;
        __syncthreads();
        unsigned wsuf = 0;
        for (int w2 = w + 1; w2 < 8; w2++) wsuf += wt[w2];
        unsigned acc = wsuf + (s - loc);       // count strictly above this thread's bins
        if (k > 0) {
#pragma unroll
            for (int jj = 7; jj >= 0; jj--) {
                int i = t * 8 + jj;
                unsigned c = sh[a][i];
                if (c && acc < (unsigned)k && acc + c >= (unsigned)k) {
                    s_bin1[a] = i;             // unique crossing thread
                    g_bin1[a][b] = i;          // duplicate identical writes across BPS blocks: benign
                    g_cab[a][b]  = acc;
                }
                acc += c;
            }
        }
        __syncthreads();
    }

    // ---------------- phase 2: register re-walk -----------------------------
    for (int i = t; i < 64; i += 256) ((unsigned*)s_tie)[i] = 0u;
    __syncthreads();

    const int b1d = s_bin1[0], b1c = s_bin1[1];
    float s0 = 0.0f, s1 = 0.0f;
#pragma unroll
    for (int j = 0; j < ITER; j++)
#pragma unroll
        for (int p = 0; p < 4; p++) {
            unsigned pk = packed[j][p];
            unsigned kd = pk & 0xFFFFu, kc = pk >> 16;
            int bd = (int)(kd >> 5), bc = (int)(kc >> 5);
            if (bd > b1d)       s0 += bf2f(kd);
            else if (bd == b1d) atomicAdd(&s_tie[0][kd & 31u], 1u);
            if (bc > b1c)       s1 += bf2f(kc);
            else if (bc == b1c) atomicAdd(&s_tie[1][kc & 31u], 1u);
        }
    for (int o = 16; o; o >>= 1) {
        s0 += __shfl_down_sync(0xffffffffu, s0, o);
        s1 += __shfl_down_sync(0xffffffffu, s1, o);
    }
    if (l == 0) { sr0[w] = s0; sr1[w] = s1; }
    __syncthreads();
    if (t == 0) {
        float a0 = 0.f, a1 = 0.f;
#pragma unroll
        for (int i = 0; i < 8; i++) { a0 += sr0[i]; a1 += sr1[i]; }
        if (a0 != 0.f) atomicAdd(&g_Sab[0][b], a0);
        if (a1 != 0.f) atomicAdd(&g_Sab[1][b], a1);
    }
    if (t < 64) {
        unsigned c = ((unsigned*)s_tie)[t];
        int a = t >> 5, bin = t & 31;
        if (c) atomicAdd(&g_cnt2[a][b][bin], c);
    }

    grid_barrier(1);

    // ---------------- phase 3: 16 units finalize -----------------------------
    if (blk < 16 && t == 0) {
        int a = blk >> 3, bb = blk & 7;
        unsigned cc = g_count[bb];
        int kk = (int)floorf((float)cc * 0.7f);
        if (kk > 0) {
            unsigned acc = g_cab[a][bb];
            float S = g_Sab[a][bb];
            int bin1 = g_bin1[a][bb];
            for (int i = 31; i >= 0; i--) {
                unsigned c = g_cnt2[a][bb][i];
                if (!c) continue;
                float v = bf2f((unsigned)((bin1 << 5) | i));   // exact bf16 code value
                if (acc + c >= (unsigned)kk) { S += (float)(kk - (int)acc) * v; break; }
                acc += c; S += (float)c * v;
            }
            float loss = S / ((float)kk + 1e-6f);
            atomicAdd(out, 0.0625f * loss);    // 0.5 * loss / 8
        }
    }

    grid_barrier(2);

    // ---------------- cleanup for next graph replay --------------------------
    {
        int gid = blk * 256 + t;
        if (gid < 2 * NB * NBINS) ((unsigned*)g_hist1)[gid] = 0u;
        if (gid < 2 * NB * 32)    ((unsigned*)g_cnt2)[gid]  = 0u;
        if (gid < 2 * NB)         ((float*)g_Sab)[gid]      = 0.f;
        if (gid < NB)             g_count[gid]              = 0u;
        // g_bar intentionally NOT reset (monotonic epochs)
    }
}

extern "C" void kernel_launch(void* const* d_in, const int* in_sizes, int n_in,
                              void* d_out, int out_size) {
    const float4* img = (const float4*)d_in[0];
    const float4* alp = (const float4*)d_in[1];
    const float4* prd = (const float4*)d_in[2];
    const int4*   tri = (const int4*)  d_in[3];
    const float4* fg  = (const float4*)d_in[4];
    const float4* bg  = (const float4*)d_in[5];
    kFused<<<GRID, 256>>>(img, alp, prd, tri, fg, bg, (float*)d_out);
}